// round 1
// baseline (speedup 1.0000x reference)
#include <cuda_runtime.h>
#include <math.h>

// ICP on GPU: 20 gated iterations of (1-NN + Kabsch + apply), then final Kabsch.
// Graph-capturable: fixed launch sequence, device-side convergence latch.

#define NPTS 8192
#define NN_BLOCKS 128   // 128 blocks x 256 threads, 4 lanes per src point
#define FR_BLOCKS 32    // final reduce: 32 blocks x 256 threads, 1 pt/thread
#define MAX_ITERS 20

__device__ float4 g_src4[NPTS];          // current src points, w = |p|^2
__device__ float4 g_B4[NPTS];            // B points, w = |b|^2
__device__ double g_part[NN_BLOCKS][16]; // per-block partial sums
__device__ float  g_T[12];               // R row-major (9) + t (3)
__device__ int    g_done;
__device__ int    g_apply;
__device__ float  g_prev_err;

// ---------------------------------------------------------------------------
__global__ void k_prep(const float* __restrict__ A, const float* __restrict__ B) {
    int i = blockIdx.x * blockDim.x + threadIdx.x;
    if (i < NPTS) {
        float ax = A[3*i], ay = A[3*i+1], az = A[3*i+2];
        g_src4[i] = make_float4(ax, ay, az, (ax*ax + ay*ay) + az*az);
        float bx = B[3*i], by = B[3*i+1], bz = B[3*i+2];
        g_B4[i]   = make_float4(bx, by, bz, (bx*bx + by*by) + bz*bz);
    }
    if (i == 0) { g_done = 0; g_apply = 0; g_prev_err = 0.f; }
}

// ---------------------------------------------------------------------------
// NN + partial reduction. 4 lanes per src point, each scans 2048 dst points.
__global__ void k_nn() {
    if (g_done) return;
    int tid  = threadIdx.x;
    int gt   = blockIdx.x * 256 + tid;
    int i    = gt >> 2;         // src point
    int part = gt & 3;          // dst partition
    float4 s = g_src4[i];
    float ss = s.w;

    int j0 = part * (NPTS / 4);
    float best = 3.4e38f;
    int   bj   = j0;
    #pragma unroll 8
    for (int j = j0; j < j0 + NPTS / 4; ++j) {
        float4 b  = g_B4[j];
        float dot = s.x*b.x + s.y*b.y + s.z*b.z;
        float d2  = (ss - 2.0f*dot) + b.w;
        if (d2 < best) { best = d2; bj = j; }
    }
    // combine the 4 partitions (lexicographic min -> first-index tie-break)
    #pragma unroll
    for (int off = 1; off < 4; off <<= 1) {
        float od2 = __shfl_xor_sync(0xffffffffu, best, off);
        int   oj  = __shfl_xor_sync(0xffffffffu, bj,   off);
        if (od2 < best || (od2 == best && oj < bj)) { best = od2; bj = oj; }
    }

    // lane 0 of each 4-lane group contributes this point's terms
    double v[16];
    #pragma unroll
    for (int q = 0; q < 16; ++q) v[q] = 0.0;
    if (part == 0) {
        float4 b = g_B4[bj];
        double sx = s.x, sy = s.y, sz = s.z;
        double bx = b.x, by = b.y, bz = b.z;
        v[0] = sx; v[1] = sy; v[2] = sz;
        v[3] = bx; v[4] = by; v[5] = bz;
        v[6]  = sx*bx; v[7]  = sx*by; v[8]  = sx*bz;
        v[9]  = sy*bx; v[10] = sy*by; v[11] = sy*bz;
        v[12] = sz*bx; v[13] = sz*by; v[14] = sz*bz;
        v[15] = (double)sqrtf(fmaxf(best, 0.0f) + 1e-12f);
    }
    // warp reduce
    #pragma unroll
    for (int q = 0; q < 16; ++q) {
        #pragma unroll
        for (int off = 16; off > 0; off >>= 1)
            v[q] += __shfl_down_sync(0xffffffffu, v[q], off);
    }
    __shared__ double sm[8][16];
    int warp = tid >> 5, lane = tid & 31;
    if (lane == 0) {
        #pragma unroll
        for (int q = 0; q < 16; ++q) sm[warp][q] = v[q];
    }
    __syncthreads();
    if (tid < 16) {
        double acc = 0.0;
        #pragma unroll
        for (int w = 0; w < 8; ++w) acc += sm[w][tid];
        g_part[blockIdx.x][tid] = acc;
    }
}

// ---------------------------------------------------------------------------
// Final reduce: sums over (A_i, src_i) pairs for the closing best-fit.
__global__ void k_fred(const float* __restrict__ A) {
    int tid = threadIdx.x;
    int i   = blockIdx.x * 256 + tid;
    double v[16];
    float ax = A[3*i], ay = A[3*i+1], az = A[3*i+2];
    float4 s = g_src4[i];
    double sx = ax, sy = ay, sz = az;          // first arg  = A
    double bx = s.x, by = s.y, bz = s.z;       // second arg = src
    v[0] = sx; v[1] = sy; v[2] = sz;
    v[3] = bx; v[4] = by; v[5] = bz;
    v[6]  = sx*bx; v[7]  = sx*by; v[8]  = sx*bz;
    v[9]  = sy*bx; v[10] = sy*by; v[11] = sy*bz;
    v[12] = sz*bx; v[13] = sz*by; v[14] = sz*bz;
    v[15] = 0.0;
    #pragma unroll
    for (int q = 0; q < 16; ++q) {
        #pragma unroll
        for (int off = 16; off > 0; off >>= 1)
            v[q] += __shfl_down_sync(0xffffffffu, v[q], off);
    }
    __shared__ double sm[8][16];
    int warp = tid >> 5, lane = tid & 31;
    if (lane == 0) {
        #pragma unroll
        for (int q = 0; q < 16; ++q) sm[warp][q] = v[q];
    }
    __syncthreads();
    if (tid < 16) {
        double acc = 0.0;
        #pragma unroll
        for (int w = 0; w < 8; ++w) acc += sm[w][tid];
        g_part[blockIdx.x][tid] = acc;
    }
}

// ---------------------------------------------------------------------------
// Kabsch: H (already divided by N), centroids -> R, t. fp32 Jacobi SVD.
__device__ void kabsch3(const float H[9], const float cA[3], const float cB[3],
                        float R[9], float t[3]) {
    // K = H^T H
    float K[3][3], V[3][3];
    #pragma unroll
    for (int i = 0; i < 3; ++i)
        #pragma unroll
        for (int j = 0; j < 3; ++j) {
            K[i][j] = H[0+i]*H[0+j] + H[3+i]*H[3+j] + H[6+i]*H[6+j];
            V[i][j] = (i == j) ? 1.0f : 0.0f;
        }
    const int pq[3][2] = {{0,1},{0,2},{1,2}};
    for (int sw = 0; sw < 8; ++sw) {
        for (int r3 = 0; r3 < 3; ++r3) {
            int p = pq[r3][0], q = pq[r3][1];
            float apq = K[p][q];
            if (fabsf(apq) < 1e-25f) continue;
            float theta = (K[q][q] - K[p][p]) / (2.0f * apq);
            float tt = 1.0f / (fabsf(theta) + sqrtf(theta*theta + 1.0f));
            if (theta < 0.0f) tt = -tt;
            float c = rsqrtf(tt*tt + 1.0f);
            float s = tt * c;
            #pragma unroll
            for (int r = 0; r < 3; ++r) {
                float kp = K[r][p], kq = K[r][q];
                K[r][p] = c*kp - s*kq; K[r][q] = s*kp + c*kq;
            }
            #pragma unroll
            for (int cc = 0; cc < 3; ++cc) {
                float kp = K[p][cc], kq = K[q][cc];
                K[p][cc] = c*kp - s*kq; K[q][cc] = s*kp + c*kq;
            }
            #pragma unroll
            for (int r = 0; r < 3; ++r) {
                float vp = V[r][p], vq = V[r][q];
                V[r][p] = c*vp - s*vq; V[r][q] = s*vp + c*vq;
            }
        }
    }
    // sort eigenvalues descending (columns of V follow)
    float lam[3] = {K[0][0], K[1][1], K[2][2]};
    int ord[3] = {0, 1, 2};
    #pragma unroll
    for (int a = 0; a < 2; ++a)
        #pragma unroll
        for (int b = 0; b < 2 - a; ++b)
            if (lam[ord[b]] < lam[ord[b+1]]) { int tmp = ord[b]; ord[b] = ord[b+1]; ord[b+1] = tmp; }
    float Vs[3][3];
    #pragma unroll
    for (int k = 0; k < 3; ++k)
        #pragma unroll
        for (int r = 0; r < 3; ++r) Vs[r][k] = V[r][ord[k]];

    // U columns: u_k = H v_k / ||H v_k||
    float U[3][3], sig[3];
    #pragma unroll
    for (int k = 0; k < 3; ++k) {
        float u0 = H[0]*Vs[0][k] + H[1]*Vs[1][k] + H[2]*Vs[2][k];
        float u1 = H[3]*Vs[0][k] + H[4]*Vs[1][k] + H[5]*Vs[2][k];
        float u2 = H[6]*Vs[0][k] + H[7]*Vs[1][k] + H[8]*Vs[2][k];
        float n = sqrtf(u0*u0 + u1*u1 + u2*u2);
        sig[k] = n;
        float inv = (n > 1e-25f) ? 1.0f / n : 0.0f;
        U[0][k] = u0*inv; U[1][k] = u1*inv; U[2][k] = u2*inv;
    }
    if (sig[2] <= 1e-10f * sig[0]) {  // degenerate smallest direction
        float u0 = U[1][0]*U[2][1] - U[2][0]*U[1][1];
        float u1 = U[2][0]*U[0][1] - U[0][0]*U[2][1];
        float u2 = U[0][0]*U[1][1] - U[1][0]*U[0][1];
        float n = rsqrtf(fmaxf(u0*u0 + u1*u1 + u2*u2, 1e-30f));
        U[0][2] = u0*n; U[1][2] = u1*n; U[2][2] = u2*n;
    }
    // R0 = V U^T; reflection fix on smallest singular vector
    float R0[3][3];
    #pragma unroll
    for (int i = 0; i < 3; ++i)
        #pragma unroll
        for (int j = 0; j < 3; ++j)
            R0[i][j] = Vs[i][0]*U[j][0] + Vs[i][1]*U[j][1] + Vs[i][2]*U[j][2];
    float det = R0[0][0]*(R0[1][1]*R0[2][2] - R0[1][2]*R0[2][1])
              - R0[0][1]*(R0[1][0]*R0[2][2] - R0[1][2]*R0[2][0])
              + R0[0][2]*(R0[1][0]*R0[2][1] - R0[1][1]*R0[2][0]);
    if (det < 0.0f) {
        #pragma unroll
        for (int i = 0; i < 3; ++i) Vs[i][2] = -Vs[i][2];
        #pragma unroll
        for (int i = 0; i < 3; ++i)
            #pragma unroll
            for (int j = 0; j < 3; ++j)
                R0[i][j] = Vs[i][0]*U[j][0] + Vs[i][1]*U[j][1] + Vs[i][2]*U[j][2];
    }
    #pragma unroll
    for (int i = 0; i < 3; ++i) {
        #pragma unroll
        for (int j = 0; j < 3; ++j) R[i*3+j] = R0[i][j];
        t[i] = cB[i] - (R0[i][0]*cA[0] + R0[i][1]*cA[1] + R0[i][2]*cA[2]);
    }
}

// ---------------------------------------------------------------------------
__global__ void k_solve(int nrows, int final_pass, float* out) {
    int tid = threadIdx.x;
    double v[16];
    #pragma unroll
    for (int q = 0; q < 16; ++q)
        v[q] = (tid < nrows) ? g_part[tid][q] : 0.0;
    #pragma unroll
    for (int q = 0; q < 16; ++q) {
        #pragma unroll
        for (int off = 16; off > 0; off >>= 1)
            v[q] += __shfl_down_sync(0xffffffffu, v[q], off);
    }
    __shared__ double sm[4][16];
    int warp = tid >> 5, lane = tid & 31;
    if (lane == 0) {
        #pragma unroll
        for (int q = 0; q < 16; ++q) sm[warp][q] = v[q];
    }
    __syncthreads();
    if (tid != 0) return;

    double S[16];
    #pragma unroll
    for (int q = 0; q < 16; ++q)
        S[q] = sm[0][q] + sm[1][q] + sm[2][q] + sm[3][q];

    if (!final_pass && g_done) { g_apply = 0; return; }

    const double N = (double)NPTS;
    double cAd[3] = {S[0]/N, S[1]/N, S[2]/N};
    double cBd[3] = {S[3]/N, S[4]/N, S[5]/N};
    float H[9], cA[3], cB[3];
    #pragma unroll
    for (int r = 0; r < 3; ++r) {
        cA[r] = (float)cAd[r]; cB[r] = (float)cBd[r];
        #pragma unroll
        for (int c = 0; c < 3; ++c)
            H[r*3+c] = (float)(S[6 + 3*r + c]/N - cAd[r]*cBd[c]);
    }
    float R[9], t[3];
    kabsch3(H, cA, cB, R, t);

    if (final_pass) {
        #pragma unroll
        for (int r = 0; r < 3; ++r) {
            out[r*4+0] = R[r*3+0]; out[r*4+1] = R[r*3+1];
            out[r*4+2] = R[r*3+2]; out[r*4+3] = t[r];
        }
        out[12] = 0.f; out[13] = 0.f; out[14] = 0.f; out[15] = 1.f;
    } else {
        #pragma unroll
        for (int q = 0; q < 9; ++q) g_T[q] = R[q];
        g_T[9] = t[0]; g_T[10] = t[1]; g_T[11] = t[2];
        float errf = (float)(S[15] / N);
        int conv = fabsf(g_prev_err - errf) < 1e-3f;
        g_prev_err = errf;
        g_apply = 1;              // transform IS applied on the detecting iteration
        if (conv) g_done = 1;
    }
}

// ---------------------------------------------------------------------------
__global__ void k_apply() {
    if (!g_apply) return;
    int i = blockIdx.x * blockDim.x + threadIdx.x;
    if (i >= NPTS) return;
    float4 s = g_src4[i];
    float x = g_T[0]*s.x + g_T[1]*s.y + g_T[2]*s.z + g_T[9];
    float y = g_T[3]*s.x + g_T[4]*s.y + g_T[5]*s.z + g_T[10];
    float z = g_T[6]*s.x + g_T[7]*s.y + g_T[8]*s.z + g_T[11];
    g_src4[i] = make_float4(x, y, z, (x*x + y*y) + z*z);
}

// ---------------------------------------------------------------------------
extern "C" void kernel_launch(void* const* d_in, const int* in_sizes, int n_in,
                              void* d_out, int out_size) {
    const float* A = (const float*)d_in[0];
    const float* B = (const float*)d_in[1];
    float* out = (float*)d_out;

    k_prep<<<(NPTS + 255) / 256, 256>>>(A, B);
    for (int it = 0; it < MAX_ITERS; ++it) {
        k_nn<<<NN_BLOCKS, 256>>>();
        k_solve<<<1, 128>>>(NN_BLOCKS, 0, nullptr);
        k_apply<<<NPTS / 256, 256>>>();
    }
    k_fred<<<FR_BLOCKS, 256>>>(A);
    k_solve<<<1, 128>>>(FR_BLOCKS, 1, out);
}